// round 2
// baseline (speedup 1.0000x reference)
#include <cuda_runtime.h>
#include <math.h>

#define Nn 384
#define Cc 128
#define NN (Nn*Nn)   // 147456

// Scratch (no allocations allowed): 4 x 75.5 MB fp32 buffers.
__device__ float g_a[NN*Cc];
__device__ float g_b[NN*Cc];
__device__ float g_g[NN*Cc];
__device__ float g_s[NN*Cc];

__device__ __forceinline__ float sigm(float x) { return 1.f / (1.f + __expf(-x)); }

// Shared-mem layout for proj/out kernels: Zs[64*128] + Wt[128*132] + mu[64] + rs[64]
#define SMF (64*128 + 128*132 + 64 + 64)     // 25216 floats = 100864 B  -> 2 blocks/SM

// ---------------------------------------------------------------------------
// Kernel 1: fused LayerNorm(z) + 5 projections (Wa1,Wa2,Wb1,Wb2,Wg)
//   tile: 64 rows x 128 cols, K=128 fully resident. 256 thr = 16x16,
//   each thread: 4 rows x 8 cols micro-tile.
// ---------------------------------------------------------------------------
__global__ __launch_bounds__(256, 2) void proj_kernel(
    const float* __restrict__ z,
    const float* __restrict__ gin, const float* __restrict__ bin,
    const float* __restrict__ Wa1, const float* __restrict__ Wa2,
    const float* __restrict__ Wb1, const float* __restrict__ Wb2,
    const float* __restrict__ Wg)
{
    extern __shared__ float sm[];
    float* Zs  = sm;               // 64*128
    float* Wt  = Zs + 64*128;      // 128*132, Wt[c*132+h] = W[h][c] (transposed, padded)
    float* muS = Wt + 128*132;     // 64
    float* rsS = muS + 64;         // 64

    const int tid = threadIdx.x;
    const int tx = tid & 15, ty = tid >> 4;
    const int base = blockIdx.x * (64*128);

    // Load raw z tile (fully coalesced float4)
    {
        const float4* zp = (const float4*)(z + base);
        float4* Zs4 = (float4*)Zs;
#pragma unroll
        for (int p = 0; p < 8; ++p) Zs4[tid + p*256] = zp[tid + p*256];
    }
    __syncthreads();

    // Row stats: 4 lanes per row, shfl combine
    {
        int row = tid >> 2, q = tid & 3;
        float s = 0.f, s2 = 0.f;
#pragma unroll
        for (int c = 0; c < 32; ++c) { float x = Zs[row*128 + q*32 + c]; s += x; s2 += x*x; }
        s  += __shfl_xor_sync(0xffffffffu, s, 1);  s2 += __shfl_xor_sync(0xffffffffu, s2, 1);
        s  += __shfl_xor_sync(0xffffffffu, s, 2);  s2 += __shfl_xor_sync(0xffffffffu, s2, 2);
        if (q == 0) {
            float mu  = s * (1.f/128.f);
            float var = fmaf(-mu, mu, s2 * (1.f/128.f));
            muS[row] = mu;
            rsS[row] = rsqrtf(var + 1e-5f);
        }
    }
    __syncthreads();

    // Normalize in place
#pragma unroll
    for (int p = 0; p < 32; ++p) {
        int e = tid + p*256;
        int r = e >> 7, c = e & 127;
        Zs[e] = (Zs[e] - muS[r]) * rsS[r] * gin[c] + bin[c];
    }

    const float* const Ws[5] = {Wa1, Wa2, Wb1, Wb2, Wg};
    const int r0 = ty*4, c0 = tx*8;
    float keep[4][8];   // sigmoid of the first matrix of each pair, kept in regs

#pragma unroll
    for (int m = 0; m < 5; ++m) {
        __syncthreads();   // protect Wt from previous iteration's readers
        const float* __restrict__ W = Ws[m];
#pragma unroll
        for (int p = 0; p < 64; ++p) {
            int e = tid + p*256;
            Wt[(e & 127)*132 + (e >> 7)] = W[e];   // transpose on store, pad 132
        }
        __syncthreads();

        float acc[4][8];
#pragma unroll
        for (int r = 0; r < 4; ++r)
#pragma unroll
            for (int c = 0; c < 8; ++c) acc[r][c] = 0.f;

#pragma unroll 8
        for (int k = 0; k < 128; ++k) {
            float4 w0 = *(const float4*)&Wt[k*132 + c0];
            float4 w1 = *(const float4*)&Wt[k*132 + c0 + 4];
#pragma unroll
            for (int r = 0; r < 4; ++r) {
                float zr = Zs[(r0 + r)*128 + k];
                acc[r][0] = fmaf(zr, w0.x, acc[r][0]);
                acc[r][1] = fmaf(zr, w0.y, acc[r][1]);
                acc[r][2] = fmaf(zr, w0.z, acc[r][2]);
                acc[r][3] = fmaf(zr, w0.w, acc[r][3]);
                acc[r][4] = fmaf(zr, w1.x, acc[r][4]);
                acc[r][5] = fmaf(zr, w1.y, acc[r][5]);
                acc[r][6] = fmaf(zr, w1.z, acc[r][6]);
                acc[r][7] = fmaf(zr, w1.w, acc[r][7]);
            }
        }

        if (m == 0 || m == 2) {
#pragma unroll
            for (int r = 0; r < 4; ++r)
#pragma unroll
                for (int c = 0; c < 8; ++c) keep[r][c] = sigm(acc[r][c]);
        } else if (m == 4) {
#pragma unroll
            for (int r = 0; r < 4; ++r) {
                float4 v0 = make_float4(sigm(acc[r][0]), sigm(acc[r][1]), sigm(acc[r][2]), sigm(acc[r][3]));
                float4 v1 = make_float4(sigm(acc[r][4]), sigm(acc[r][5]), sigm(acc[r][6]), sigm(acc[r][7]));
                *(float4*)&g_g[base + (r0 + r)*128 + c0]     = v0;
                *(float4*)&g_g[base + (r0 + r)*128 + c0 + 4] = v1;
            }
        } else {
            float* __restrict__ dst = (m == 1) ? g_a : g_b;
#pragma unroll
            for (int r = 0; r < 4; ++r) {
                float4 v0 = make_float4(keep[r][0]*acc[r][0], keep[r][1]*acc[r][1],
                                        keep[r][2]*acc[r][2], keep[r][3]*acc[r][3]);
                float4 v1 = make_float4(keep[r][4]*acc[r][4], keep[r][5]*acc[r][5],
                                        keep[r][6]*acc[r][6], keep[r][7]*acc[r][7]);
                *(float4*)&dst[base + (r0 + r)*128 + c0]     = v0;
                *(float4*)&dst[base + (r0 + r)*128 + c0 + 4] = v1;
            }
        }
    }
}

// ---------------------------------------------------------------------------
// Kernel 2: einsum  S[i,j,d] = sum_k a[i,k,d]*b[j,k,d]
//   Per block: 64 i x 64 j x 4 d (float4 over channel dim). 256 thr = 16x16,
//   strided thread->row/col mapping (i = ty + r*16, j = tx + c*16) so Bs reads
//   are 256B-contiguous per warp (conflict-free) and As reads are broadcasts.
// ---------------------------------------------------------------------------
__global__ __launch_bounds__(256, 2) void einsum_kernel()
{
    __shared__ float4 As[16*64];   // [kk][i], 16 KB
    __shared__ float4 Bs[16*64];   // [kk][j], 16 KB

    const int tid = threadIdx.x;
    const int tx = tid & 15, ty = tid >> 4;
    const int i0 = blockIdx.y * 64, j0 = blockIdx.x * 64;
    const int d4 = blockIdx.z;     // float4 index of channel chunk

    const float4* __restrict__ A4 = (const float4*)g_a;
    const float4* __restrict__ B4 = (const float4*)g_b;

    float4 acc[4][4];
#pragma unroll
    for (int r = 0; r < 4; ++r)
#pragma unroll
        for (int c = 0; c < 4; ++c) acc[r][c] = make_float4(0.f, 0.f, 0.f, 0.f);

    for (int kb = 0; kb < Nn; kb += 16) {
        __syncthreads();
#pragma unroll
        for (int p = 0; p < 4; ++p) {
            int e  = tid + p*256;
            int kk = e >> 6, ii = e & 63;
            As[kk*64 + ii] = A4[((i0 + ii)*Nn + kb + kk)*32 + d4];
            Bs[kk*64 + ii] = B4[((j0 + ii)*Nn + kb + kk)*32 + d4];
        }
        __syncthreads();

#pragma unroll
        for (int kk = 0; kk < 16; ++kk) {
            float4 av[4], bv[4];
#pragma unroll
            for (int r = 0; r < 4; ++r) av[r] = As[kk*64 + ty + r*16];
#pragma unroll
            for (int c = 0; c < 4; ++c) bv[c] = Bs[kk*64 + tx + c*16];
#pragma unroll
            for (int r = 0; r < 4; ++r)
#pragma unroll
                for (int c = 0; c < 4; ++c) {
                    acc[r][c].x = fmaf(av[r].x, bv[c].x, acc[r][c].x);
                    acc[r][c].y = fmaf(av[r].y, bv[c].y, acc[r][c].y);
                    acc[r][c].z = fmaf(av[r].z, bv[c].z, acc[r][c].z);
                    acc[r][c].w = fmaf(av[r].w, bv[c].w, acc[r][c].w);
                }
        }
    }

    float4* __restrict__ S4 = (float4*)g_s;
#pragma unroll
    for (int r = 0; r < 4; ++r)
#pragma unroll
        for (int c = 0; c < 4; ++c)
            S4[((i0 + ty + r*16)*Nn + (j0 + tx + c*16))*32 + d4] = acc[r][c];
}

// ---------------------------------------------------------------------------
// Kernel 3: fused LayerNorm(s) + Wout projection + gating
// ---------------------------------------------------------------------------
__global__ __launch_bounds__(256, 2) void out_kernel(
    const float* __restrict__ gout, const float* __restrict__ bout,
    const float* __restrict__ Wout, float* __restrict__ out)
{
    extern __shared__ float sm[];
    float* Ss  = sm;
    float* Wt  = Ss + 64*128;
    float* muS = Wt + 128*132;
    float* rsS = muS + 64;

    const int tid = threadIdx.x;
    const int tx = tid & 15, ty = tid >> 4;
    const int base = blockIdx.x * (64*128);

    {
        const float4* sp = (const float4*)(g_s + base);
        float4* Ss4 = (float4*)Ss;
#pragma unroll
        for (int p = 0; p < 8; ++p) Ss4[tid + p*256] = sp[tid + p*256];
    }
#pragma unroll
    for (int p = 0; p < 64; ++p) {
        int e = tid + p*256;
        Wt[(e & 127)*132 + (e >> 7)] = Wout[e];    // Wt[h*132+d] = Wout[d][h]
    }
    __syncthreads();

    {
        int row = tid >> 2, q = tid & 3;
        float s = 0.f, s2 = 0.f;
#pragma unroll
        for (int c = 0; c < 32; ++c) { float x = Ss[row*128 + q*32 + c]; s += x; s2 += x*x; }
        s  += __shfl_xor_sync(0xffffffffu, s, 1);  s2 += __shfl_xor_sync(0xffffffffu, s2, 1);
        s  += __shfl_xor_sync(0xffffffffu, s, 2);  s2 += __shfl_xor_sync(0xffffffffu, s2, 2);
        if (q == 0) {
            float mu  = s * (1.f/128.f);
            float var = fmaf(-mu, mu, s2 * (1.f/128.f));
            muS[row] = mu;
            rsS[row] = rsqrtf(var + 1e-5f);
        }
    }
    __syncthreads();
#pragma unroll
    for (int p = 0; p < 32; ++p) {
        int e = tid + p*256;
        int r = e >> 7, c = e & 127;
        Ss[e] = (Ss[e] - muS[r]) * rsS[r] * gout[c] + bout[c];
    }
    __syncthreads();

    const int r0 = ty*4, c0 = tx*8;
    float acc[4][8];
#pragma unroll
    for (int r = 0; r < 4; ++r)
#pragma unroll
        for (int c = 0; c < 8; ++c) acc[r][c] = 0.f;

#pragma unroll 8
    for (int k = 0; k < 128; ++k) {
        float4 w0 = *(const float4*)&Wt[k*132 + c0];
        float4 w1 = *(const float4*)&Wt[k*132 + c0 + 4];
#pragma unroll
        for (int r = 0; r < 4; ++r) {
            float zr = Ss[(r0 + r)*128 + k];
            acc[r][0] = fmaf(zr, w0.x, acc[r][0]);
            acc[r][1] = fmaf(zr, w0.y, acc[r][1]);
            acc[r][2] = fmaf(zr, w0.z, acc[r][2]);
            acc[r][3] = fmaf(zr, w0.w, acc[r][3]);
            acc[r][4] = fmaf(zr, w1.x, acc[r][4]);
            acc[r][5] = fmaf(zr, w1.y, acc[r][5]);
            acc[r][6] = fmaf(zr, w1.z, acc[r][6]);
            acc[r][7] = fmaf(zr, w1.w, acc[r][7]);
        }
    }

#pragma unroll
    for (int r = 0; r < 4; ++r) {
        const float4 gv0 = *(const float4*)&g_g[base + (r0 + r)*128 + c0];
        const float4 gv1 = *(const float4*)&g_g[base + (r0 + r)*128 + c0 + 4];
        float4 v0 = make_float4(gv0.x*acc[r][0], gv0.y*acc[r][1], gv0.z*acc[r][2], gv0.w*acc[r][3]);
        float4 v1 = make_float4(gv1.x*acc[r][4], gv1.y*acc[r][5], gv1.z*acc[r][6], gv1.w*acc[r][7]);
        *(float4*)&out[base + (r0 + r)*128 + c0]     = v0;
        *(float4*)&out[base + (r0 + r)*128 + c0 + 4] = v1;
    }
}

// ---------------------------------------------------------------------------
extern "C" void kernel_launch(void* const* d_in, const int* in_sizes, int n_in,
                              void* d_out, int out_size)
{
    const float* z    = (const float*)d_in[0];
    const float* gin  = (const float*)d_in[1];
    const float* bin  = (const float*)d_in[2];
    const float* gout = (const float*)d_in[3];
    const float* bout = (const float*)d_in[4];
    const float* Wa1  = (const float*)d_in[5];
    const float* Wa2  = (const float*)d_in[6];
    const float* Wb1  = (const float*)d_in[7];
    const float* Wb2  = (const float*)d_in[8];
    const float* Wg   = (const float*)d_in[9];
    const float* Wout = (const float*)d_in[10];
    float* out = (float*)d_out;

    const int smem = SMF * (int)sizeof(float);   // 100864 B
    cudaFuncSetAttribute(proj_kernel, cudaFuncAttributeMaxDynamicSharedMemorySize, smem);
    cudaFuncSetAttribute(out_kernel,  cudaFuncAttributeMaxDynamicSharedMemorySize, smem);

    proj_kernel<<<NN/64, 256, smem>>>(z, gin, bin, Wa1, Wa2, Wb1, Wb2, Wg);
    einsum_kernel<<<dim3(Nn/64, Nn/64, Cc/4), 256>>>();
    out_kernel<<<NN/64, 256, smem>>>(gout, bout, Wout, out);
}

// round 6
// speedup vs baseline: 3.9399x; 3.9399x over previous
#include <cuda_runtime.h>
#include <cuda_bf16.h>
#include <math.h>

#define Nn 384
#define Cc 128
#define NN (Nn*Nn)   // 147456

// ---------------- global scratch (no allocations allowed) ------------------
// a,b as bf16 hi/lo channel-major planes [d][i*384+k]
__device__ __nv_bfloat16 g_ah[(size_t)Cc*NN];
__device__ __nv_bfloat16 g_al[(size_t)Cc*NN];
__device__ __nv_bfloat16 g_bh[(size_t)Cc*NN];
__device__ __nv_bfloat16 g_bl[(size_t)Cc*NN];
// gate as [ij][h] fp32; s as fp32 planes [d][i*384+j]
__device__ float g_gate[(size_t)Cc*NN];
__device__ float g_s[(size_t)Cc*NN];

// ---------------- helpers ---------------------------------------------------
__device__ __forceinline__ unsigned smem_u32(const void* p) {
    unsigned a;
    asm("{ .reg .u64 t; cvta.to.shared.u64 t, %1; cvt.u32.u64 %0, t; }" : "=r"(a) : "l"(p));
    return a;
}
__device__ __forceinline__ void ldsm4(unsigned r[4], unsigned addr) {
    asm volatile("ldmatrix.sync.aligned.m8n8.x4.shared.b16 {%0,%1,%2,%3}, [%4];"
        : "=r"(r[0]), "=r"(r[1]), "=r"(r[2]), "=r"(r[3]) : "r"(addr));
}
__device__ __forceinline__ void mma_bf16(float c[4], const unsigned a[4], unsigned b0, unsigned b1) {
    asm volatile("mma.sync.aligned.m16n8k16.row.col.f32.bf16.bf16.f32 "
        "{%0,%1,%2,%3}, {%4,%5,%6,%7}, {%8,%9}, {%0,%1,%2,%3};"
        : "+f"(c[0]), "+f"(c[1]), "+f"(c[2]), "+f"(c[3])
        : "r"(a[0]), "r"(a[1]), "r"(a[2]), "r"(a[3]), "r"(b0), "r"(b1));
}
// lane address for ldmatrix.x4 covering a 16x16 bf16 block at (r0,c0), row stride S (bf16 elems)
__device__ __forceinline__ unsigned ldsm_addr(unsigned base, int lane, int r0, int c0, int S) {
    int row = r0 + (lane & 7) + ((lane >> 3) & 1) * 8;
    int col = c0 + ((lane >> 4) << 3);
    return base + (unsigned)((row * S + col) * 2);
}
__device__ __forceinline__ float sigm(float x) { return 1.f / (1.f + __expf(-x)); }

__device__ __forceinline__ void split2(float a, float b, unsigned& hi, unsigned& lo) {
    __nv_bfloat16 ha = __float2bfloat16(a), hb = __float2bfloat16(b);
    float ra = a - __bfloat162float(ha), rb = b - __bfloat162float(hb);
    __nv_bfloat16 la = __float2bfloat16(ra), lb = __float2bfloat16(rb);
    hi = (unsigned)__bfloat16_as_ushort(ha) | ((unsigned)__bfloat16_as_ushort(hb) << 16);
    lo = (unsigned)__bfloat16_as_ushort(la) | ((unsigned)__bfloat16_as_ushort(lb) << 16);
}
__device__ __forceinline__ void store_split(__nv_bfloat16* ph, __nv_bfloat16* pl, size_t off, float v) {
    __nv_bfloat16 h = __float2bfloat16(v);
    ph[off] = h;
    pl[off] = __float2bfloat16(v - __bfloat162float(h));
}

// ---------------- shared layouts (proj / out kernels) -----------------------
#define STR 136                 // bf16 row stride for 128-wide operand tiles (272B, odd*16B)
#define OFF_AHI 0
#define OFF_ALO 34816
#define OFF_B   69632           // Bhi here; also aliases fp32 staging [128][133]
#define OFF_BLO (69632 + 34816)
#define OFF_GIN 139264
#define OFF_BIN 139776
#define PO_SMEM 140288

// ===========================================================================
// Kernel 1: LN(z) + 5 projections.  512 thr, 16 warps (warp = m16 x n64).
// ===========================================================================
__global__ __launch_bounds__(512, 1) void proj_kernel(
    const float* __restrict__ z,
    const float* __restrict__ gin, const float* __restrict__ bin,
    const float* __restrict__ Wa1, const float* __restrict__ Wa2,
    const float* __restrict__ Wb1, const float* __restrict__ Wb2,
    const float* __restrict__ Wg)
{
    extern __shared__ char sm[];
    const unsigned SB = smem_u32(sm);
    const int tid = threadIdx.x, lane = tid & 31, w = tid >> 5;
    const int g = lane >> 2, t2 = (lane & 3) * 2;
    const int wm = w >> 1, wn = w & 1;      // m-tile 0..7, n-half 0..1
    const int m0 = wm * 16;
    const size_t base = (size_t)blockIdx.x * 128;

    if (tid < 128) {
        ((float*)(sm + OFF_GIN))[tid] = gin[tid];
        ((float*)(sm + OFF_BIN))[tid] = bin[tid];
    }

    // stage z tile fp32 [128][133]
    float* Zf = (float*)(sm + OFF_B);
    {
        const float4* z4 = (const float4*)(z + base * 128);
#pragma unroll
        for (int p = 0; p < 8; ++p) {
            int f = tid + p * 512;
            float4 v = z4[f];
            int ij = f >> 5, c4 = (f & 31) * 4;
            float* d = &Zf[ij * 133 + c4];
            d[0] = v.x; d[1] = v.y; d[2] = v.z; d[3] = v.w;
        }
    }
    __syncthreads();

    // LN: 4 threads per row
    {
        int row = tid >> 2, q = tid & 3;
        float s = 0.f, s2 = 0.f;
#pragma unroll
        for (int c = 0; c < 32; ++c) { float x = Zf[row * 133 + q * 32 + c]; s += x; s2 += x * x; }
        s  += __shfl_xor_sync(0xffffffffu, s, 1);  s2 += __shfl_xor_sync(0xffffffffu, s2, 1);
        s  += __shfl_xor_sync(0xffffffffu, s, 2);  s2 += __shfl_xor_sync(0xffffffffu, s2, 2);
        float mu = s * (1.f / 128.f);
        float rs = rsqrtf(fmaf(-mu, mu, s2 * (1.f / 128.f)) + 1e-5f);
        const float* G  = (const float*)(sm + OFF_GIN);
        const float* Bv = (const float*)(sm + OFF_BIN);
#pragma unroll
        for (int c2 = 0; c2 < 16; ++c2) {
            int c = q * 32 + c2 * 2;
            float x0 = (Zf[row * 133 + c]     - mu) * rs * G[c]     + Bv[c];
            float x1 = (Zf[row * 133 + c + 1] - mu) * rs * G[c + 1] + Bv[c + 1];
            unsigned hi, lo; split2(x0, x1, hi, lo);
            *(unsigned*)(sm + OFF_AHI + (row * STR + c) * 2) = hi;
            *(unsigned*)(sm + OFF_ALO + (row * STR + c) * 2) = lo;
        }
    }

    const float* const Wlist[5] = {Wa1, Wa2, Wb1, Wb2, Wg};
    float keep[8][4];

    for (int m = 0; m < 5; ++m) {
        __syncthreads();   // Zf / previous B fully consumed
        {
            const float4* W4 = (const float4*)Wlist[m];
#pragma unroll
            for (int p = 0; p < 8; ++p) {
                int f = tid + p * 512;
                float4 v = W4[f];
                int h = f >> 5, c4 = (f & 31) * 4;
                unsigned h0, l0, h1, l1;
                split2(v.x, v.y, h0, l0);
                split2(v.z, v.w, h1, l1);
                *(uint2*)(sm + OFF_B   + (h * STR + c4) * 2) = make_uint2(h0, h1);
                *(uint2*)(sm + OFF_BLO + (h * STR + c4) * 2) = make_uint2(l0, l1);
            }
        }
        __syncthreads();

        float acc[8][4];
#pragma unroll
        for (int i = 0; i < 8; ++i)
#pragma unroll
            for (int j = 0; j < 4; ++j) acc[i][j] = 0.f;

#pragma unroll
        for (int ks = 0; ks < 8; ++ks) {
            const int k0 = ks * 16;
            unsigned ah[4], al[4];
            ldsm4(ah, ldsm_addr(SB + OFF_AHI, lane, m0, k0, STR));
            ldsm4(al, ldsm_addr(SB + OFF_ALO, lane, m0, k0, STR));
#pragma unroll
            for (int nb = 0; nb < 4; ++nb) {
                const int n0 = wn * 64 + nb * 16;
                unsigned bh[4], bl[4];
                ldsm4(bh, ldsm_addr(SB + OFF_B,   lane, n0, k0, STR));
                ldsm4(bl, ldsm_addr(SB + OFF_BLO, lane, n0, k0, STR));
                mma_bf16(acc[nb * 2],     ah, bh[0], bh[2]);
                mma_bf16(acc[nb * 2],     ah, bl[0], bl[2]);
                mma_bf16(acc[nb * 2],     al, bh[0], bh[2]);
                mma_bf16(acc[nb * 2 + 1], ah, bh[1], bh[3]);
                mma_bf16(acc[nb * 2 + 1], ah, bl[1], bl[3]);
                mma_bf16(acc[nb * 2 + 1], al, bh[1], bh[3]);
            }
        }

        // epilogues (registers + gmem only)
        if (m == 0 || m == 2) {
#pragma unroll
            for (int i = 0; i < 8; ++i)
#pragma unroll
                for (int j = 0; j < 4; ++j) keep[i][j] = sigm(acc[i][j]);
        } else if (m == 1 || m == 3) {
            __nv_bfloat16* ph = (m == 1) ? g_ah : g_bh;
            __nv_bfloat16* pl = (m == 1) ? g_al : g_bl;
            const size_t ijA = base + m0 + g, ijB = ijA + 8;
#pragma unroll
            for (int nt = 0; nt < 8; ++nt) {
                const size_t d0 = (size_t)(wn * 64 + nt * 8 + t2);
                store_split(ph, pl, d0 * NN + ijA,       keep[nt][0] * acc[nt][0]);
                store_split(ph, pl, (d0 + 1) * NN + ijA, keep[nt][1] * acc[nt][1]);
                store_split(ph, pl, d0 * NN + ijB,       keep[nt][2] * acc[nt][2]);
                store_split(ph, pl, (d0 + 1) * NN + ijB, keep[nt][3] * acc[nt][3]);
            }
        } else {
            const size_t ijA = base + m0 + g, ijB = ijA + 8;
#pragma unroll
            for (int nt = 0; nt < 8; ++nt) {
                const int c0 = wn * 64 + nt * 8 + t2;
                *(float2*)&g_gate[ijA * 128 + c0] = make_float2(sigm(acc[nt][0]), sigm(acc[nt][1]));
                *(float2*)&g_gate[ijB * 128 + c0] = make_float2(sigm(acc[nt][2]), sigm(acc[nt][3]));
            }
        }
    }
}

// ===========================================================================
// Kernel 2: einsum S[i,j|d] = sum_k a[i,k|d] b[j,k|d]   (128 batched GEMMs)
// CTA = 128x128 tile, 256 thr (8 warps, 2x4), K chunks of 64.
// ===========================================================================
#define ESTR 72
#define E_AHI 0
#define E_ALO 18432
#define E_BHI 36864
#define E_BLO 55296
#define E_SMEM 73728

__global__ __launch_bounds__(256, 2) void einsum_kernel()
{
    extern __shared__ char sm[];
    const unsigned SB = smem_u32(sm);
    const int tid = threadIdx.x, lane = tid & 31, w = tid >> 5;
    const int g = lane >> 2, t2 = (lane & 3) * 2;
    const int wr = w >> 2, wc = w & 3;          // 2 x 4 warps
    const int m0w = wr * 64, n0w = wc * 32;
    const int d = blockIdx.z, i0 = blockIdx.y * 128, j0 = blockIdx.x * 128;

    const __nv_bfloat16* pah = g_ah + (size_t)d * NN;
    const __nv_bfloat16* pal = g_al + (size_t)d * NN;
    const __nv_bfloat16* pbh = g_bh + (size_t)d * NN;
    const __nv_bfloat16* pbl = g_bl + (size_t)d * NN;

    float acc[16][4];
#pragma unroll
    for (int i = 0; i < 16; ++i)
#pragma unroll
        for (int j = 0; j < 4; ++j) acc[i][j] = 0.f;

    for (int c = 0; c < 6; ++c) {
        const int k0g = c * 64;
        __syncthreads();
#pragma unroll
        for (int p = 0; p < 4; ++p) {
            int f = tid + p * 256;
            int r = f >> 3, sg = f & 7;
            size_t oA = (size_t)(i0 + r) * Nn + k0g + sg * 8;
            size_t oB = (size_t)(j0 + r) * Nn + k0g + sg * 8;
            unsigned so = (unsigned)((r * ESTR + sg * 8) * 2);
            *(uint4*)(sm + E_AHI + so) = *(const uint4*)(pah + oA);
            *(uint4*)(sm + E_ALO + so) = *(const uint4*)(pal + oA);
            *(uint4*)(sm + E_BHI + so) = *(const uint4*)(pbh + oB);
            *(uint4*)(sm + E_BLO + so) = *(const uint4*)(pbl + oB);
        }
        __syncthreads();

#pragma unroll
        for (int ks = 0; ks < 4; ++ks) {
            const int k0 = ks * 16;
            unsigned bh[4][2], bl[4][2];
#pragma unroll
            for (int nb = 0; nb < 2; ++nb) {
                unsigned tb[4];
                ldsm4(tb, ldsm_addr(SB + E_BHI, lane, n0w + nb * 16, k0, ESTR));
                bh[nb * 2][0] = tb[0]; bh[nb * 2][1] = tb[2];
                bh[nb * 2 + 1][0] = tb[1]; bh[nb * 2 + 1][1] = tb[3];
                ldsm4(tb, ldsm_addr(SB + E_BLO, lane, n0w + nb * 16, k0, ESTR));
                bl[nb * 2][0] = tb[0]; bl[nb * 2][1] = tb[2];
                bl[nb * 2 + 1][0] = tb[1]; bl[nb * 2 + 1][1] = tb[3];
            }
#pragma unroll
            for (int mt = 0; mt < 4; ++mt) {
                unsigned ah[4], al[4];
                ldsm4(ah, ldsm_addr(SB + E_AHI, lane, m0w + mt * 16, k0, ESTR));
                ldsm4(al, ldsm_addr(SB + E_ALO, lane, m0w + mt * 16, k0, ESTR));
#pragma unroll
                for (int n = 0; n < 4; ++n) {
                    mma_bf16(acc[mt * 4 + n], ah, bh[n][0], bh[n][1]);
                    mma_bf16(acc[mt * 4 + n], ah, bl[n][0], bl[n][1]);
                    mma_bf16(acc[mt * 4 + n], al, bh[n][0], bh[n][1]);
                }
            }
        }
    }

    float* plane = g_s + (size_t)d * NN;
#pragma unroll
    for (int mt = 0; mt < 4; ++mt)
#pragma unroll
        for (int n = 0; n < 4; ++n) {
            int row = m0w + mt * 16 + g;
            int col = n0w + n * 8 + t2;
            float* pr = plane + (size_t)(i0 + row) * Nn + (j0 + col);
            *(float2*)pr             = make_float2(acc[mt * 4 + n][0], acc[mt * 4 + n][1]);
            *(float2*)(pr + 8 * Nn)  = make_float2(acc[mt * 4 + n][2], acc[mt * 4 + n][3]);
        }
}

// ===========================================================================
// Kernel 3: LN(s over d) + Wout + gate.  512 thr, same tiling as proj.
// ===========================================================================
__global__ __launch_bounds__(512, 1) void out_kernel(
    const float* __restrict__ gout, const float* __restrict__ bout,
    const float* __restrict__ Wout, float* __restrict__ outp)
{
    extern __shared__ char sm[];
    const unsigned SB = smem_u32(sm);
    const int tid = threadIdx.x, lane = tid & 31, w = tid >> 5;
    const int g = lane >> 2, t2 = (lane & 3) * 2;
    const int wm = w >> 1, wn = w & 1;
    const int m0 = wm * 16;
    const size_t base = (size_t)blockIdx.x * 128;

    if (tid < 128) {
        ((float*)(sm + OFF_GIN))[tid] = gout[tid];
        ((float*)(sm + OFF_BIN))[tid] = bout[tid];
    }

    // transposed stage: Sf[ij][d], fp32, stride 133
    float* Sf = (float*)(sm + OFF_B);
#pragma unroll 4
    for (int p = 0; p < 32; ++p) {
        int f = tid + p * 512;
        int ij = f & 127, dd = f >> 7;
        Sf[ij * 133 + dd] = g_s[(size_t)dd * NN + base + ij];
    }
    __syncthreads();

    {
        int row = tid >> 2, q = tid & 3;
        float s = 0.f, s2 = 0.f;
#pragma unroll
        for (int c = 0; c < 32; ++c) { float x = Sf[row * 133 + q * 32 + c]; s += x; s2 += x * x; }
        s  += __shfl_xor_sync(0xffffffffu, s, 1);  s2 += __shfl_xor_sync(0xffffffffu, s2, 1);
        s  += __shfl_xor_sync(0xffffffffu, s, 2);  s2 += __shfl_xor_sync(0xffffffffu, s2, 2);
        float mu = s * (1.f / 128.f);
        float rs = rsqrtf(fmaf(-mu, mu, s2 * (1.f / 128.f)) + 1e-5f);
        const float* G  = (const float*)(sm + OFF_GIN);
        const float* Bv = (const float*)(sm + OFF_BIN);
#pragma unroll
        for (int c2 = 0; c2 < 16; ++c2) {
            int c = q * 32 + c2 * 2;
            float x0 = (Sf[row * 133 + c]     - mu) * rs * G[c]     + Bv[c];
            float x1 = (Sf[row * 133 + c + 1] - mu) * rs * G[c + 1] + Bv[c + 1];
            unsigned hi, lo; split2(x0, x1, hi, lo);
            *(unsigned*)(sm + OFF_AHI + (row * STR + c) * 2) = hi;
            *(unsigned*)(sm + OFF_ALO + (row * STR + c) * 2) = lo;
        }
    }
    __syncthreads();   // Sf fully consumed -> B tiles may overwrite

    {
        const float4* W4 = (const float4*)Wout;
#pragma unroll
        for (int p = 0; p < 8; ++p) {
            int f = tid + p * 512;
            float4 v = W4[f];
            int h = f >> 5, c4 = (f & 31) * 4;
            unsigned h0, l0, h1, l1;
            split2(v.x, v.y, h0, l0);
            split2(v.z, v.w, h1, l1);
            *(uint2*)(sm + OFF_B   + (h * STR + c4) * 2) = make_uint2(h0, h1);
            *(uint2*)(sm + OFF_BLO + (h * STR + c4) * 2) = make_uint2(l0, l1);
        }
    }
    __syncthreads();

    float acc[8][4];
#pragma unroll
    for (int i = 0; i < 8; ++i)
#pragma unroll
        for (int j = 0; j < 4; ++j) acc[i][j] = 0.f;

#pragma unroll
    for (int ks = 0; ks < 8; ++ks) {
        const int k0 = ks * 16;
        unsigned ah[4], al[4];
        ldsm4(ah, ldsm_addr(SB + OFF_AHI, lane, m0, k0, STR));
        ldsm4(al, ldsm_addr(SB + OFF_ALO, lane, m0, k0, STR));
#pragma unroll
        for (int nb = 0; nb < 4; ++nb) {
            const int n0 = wn * 64 + nb * 16;
            unsigned bh[4], bl[4];
            ldsm4(bh, ldsm_addr(SB + OFF_B,   lane, n0, k0, STR));
            ldsm4(bl, ldsm_addr(SB + OFF_BLO, lane, n0, k0, STR));
            mma_bf16(acc[nb * 2],     ah, bh[0], bh[2]);
            mma_bf16(acc[nb * 2],     ah, bl[0], bl[2]);
            mma_bf16(acc[nb * 2],     al, bh[0], bh[2]);
            mma_bf16(acc[nb * 2 + 1], ah, bh[1], bh[3]);
            mma_bf16(acc[nb * 2 + 1], ah, bl[1], bl[3]);
            mma_bf16(acc[nb * 2 + 1], al, bh[1], bh[3]);
        }
    }

    const size_t ijA = base + m0 + g, ijB = ijA + 8;
#pragma unroll
    for (int nt = 0; nt < 8; ++nt) {
        const int c0 = wn * 64 + nt * 8 + t2;
        float2 g0 = *(const float2*)&g_gate[ijA * 128 + c0];
        float2 g1 = *(const float2*)&g_gate[ijB * 128 + c0];
        *(float2*)&outp[ijA * 128 + c0] = make_float2(acc[nt][0] * g0.x, acc[nt][1] * g0.y);
        *(float2*)&outp[ijB * 128 + c0] = make_float2(acc[nt][2] * g1.x, acc[nt][3] * g1.y);
    }
}

// ---------------------------------------------------------------------------
extern "C" void kernel_launch(void* const* d_in, const int* in_sizes, int n_in,
                              void* d_out, int out_size)
{
    const float* z    = (const float*)d_in[0];
    const float* gin  = (const float*)d_in[1];
    const float* bin  = (const float*)d_in[2];
    const float* gout = (const float*)d_in[3];
    const float* bout = (const float*)d_in[4];
    const float* Wa1  = (const float*)d_in[5];
    const float* Wa2  = (const float*)d_in[6];
    const float* Wb1  = (const float*)d_in[7];
    const float* Wb2  = (const float*)d_in[8];
    const float* Wg   = (const float*)d_in[9];
    const float* Wout = (const float*)d_in[10];
    float* out = (float*)d_out;

    cudaFuncSetAttribute(proj_kernel,   cudaFuncAttributeMaxDynamicSharedMemorySize, PO_SMEM);
    cudaFuncSetAttribute(einsum_kernel, cudaFuncAttributeMaxDynamicSharedMemorySize, E_SMEM);
    cudaFuncSetAttribute(out_kernel,    cudaFuncAttributeMaxDynamicSharedMemorySize, PO_SMEM);

    proj_kernel<<<NN / 128, 512, PO_SMEM>>>(z, gin, bin, Wa1, Wa2, Wb1, Wb2, Wg);
    einsum_kernel<<<dim3(Nn / 128, Nn / 128, Cc), 256, E_SMEM>>>();
    out_kernel<<<NN / 128, 512, PO_SMEM>>>(gout, bout, Wout, out);
}

// round 7
// speedup vs baseline: 4.3573x; 1.1059x over previous
#include <cuda_runtime.h>
#include <cuda_bf16.h>
#include <math.h>

#define Nn 384
#define Cc 128
#define NN (Nn*Nn)   // 147456

// ---------------- global scratch (no allocations allowed) ------------------
__device__ __nv_bfloat16 g_ah[(size_t)Cc*NN];
__device__ __nv_bfloat16 g_al[(size_t)Cc*NN];
__device__ __nv_bfloat16 g_bh[(size_t)Cc*NN];
__device__ __nv_bfloat16 g_bl[(size_t)Cc*NN];
__device__ float g_gate[(size_t)Cc*NN];
__device__ float g_s[(size_t)Cc*NN];

// Pre-split weights, stored as the exact smem tile image:
// per matrix: hi plane [128 rows x 272B] then lo plane. 6 matrices.
#define WPLANE 34816               // 128 * 272
#define WMAT   (2*WPLANE)          // 69632
__device__ __align__(16) char g_wsp[6*WMAT];

// ---------------- helpers ---------------------------------------------------
__device__ __forceinline__ unsigned smem_u32(const void* p) {
    unsigned a;
    asm("{ .reg .u64 t; cvta.to.shared.u64 t, %1; cvt.u32.u64 %0, t; }" : "=r"(a) : "l"(p));
    return a;
}
__device__ __forceinline__ void ldsm4(unsigned r[4], unsigned addr) {
    asm volatile("ldmatrix.sync.aligned.m8n8.x4.shared.b16 {%0,%1,%2,%3}, [%4];"
        : "=r"(r[0]), "=r"(r[1]), "=r"(r[2]), "=r"(r[3]) : "r"(addr));
}
__device__ __forceinline__ void mma_bf16(float c[4], const unsigned a[4], unsigned b0, unsigned b1) {
    asm volatile("mma.sync.aligned.m16n8k16.row.col.f32.bf16.bf16.f32 "
        "{%0,%1,%2,%3}, {%4,%5,%6,%7}, {%8,%9}, {%0,%1,%2,%3};"
        : "+f"(c[0]), "+f"(c[1]), "+f"(c[2]), "+f"(c[3])
        : "r"(a[0]), "r"(a[1]), "r"(a[2]), "r"(a[3]), "r"(b0), "r"(b1));
}
__device__ __forceinline__ unsigned ldsm_addr(unsigned base, int lane, int r0, int c0, int S) {
    int row = r0 + (lane & 7) + ((lane >> 3) & 1) * 8;
    int col = c0 + ((lane >> 4) << 3);
    return base + (unsigned)((row * S + col) * 2);
}
__device__ __forceinline__ void cp16(unsigned dst, const void* src) {
    asm volatile("cp.async.cg.shared.global [%0], [%1], 16;" :: "r"(dst), "l"(src));
}
#define CP_COMMIT() asm volatile("cp.async.commit_group;" ::: "memory")
#define CP_WAIT0()  asm volatile("cp.async.wait_group 0;" ::: "memory")

__device__ __forceinline__ float sigm(float x) { return 1.f / (1.f + __expf(-x)); }

__device__ __forceinline__ void split2(float a, float b, unsigned& hi, unsigned& lo) {
    __nv_bfloat16 ha = __float2bfloat16(a), hb = __float2bfloat16(b);
    float ra = a - __bfloat162float(ha), rb = b - __bfloat162float(hb);
    __nv_bfloat16 la = __float2bfloat16(ra), lb = __float2bfloat16(rb);
    hi = (unsigned)__bfloat16_as_ushort(ha) | ((unsigned)__bfloat16_as_ushort(hb) << 16);
    lo = (unsigned)__bfloat16_as_ushort(la) | ((unsigned)__bfloat16_as_ushort(lb) << 16);
}
__device__ __forceinline__ void store_split(__nv_bfloat16* ph, __nv_bfloat16* pl, size_t off, float v) {
    __nv_bfloat16 h = __float2bfloat16(v);
    ph[off] = h;
    pl[off] = __float2bfloat16(v - __bfloat162float(h));
}

#define STR 136      // bf16 row stride for 128-wide tiles (272B)

// ===========================================================================
// Kernel 0: split 6 weight matrices into smem-image layout (hi/lo, 272B rows)
// ===========================================================================
__global__ __launch_bounds__(256) void split_weights_kernel(
    const float* __restrict__ Wa1, const float* __restrict__ Wa2,
    const float* __restrict__ Wb1, const float* __restrict__ Wb2,
    const float* __restrict__ Wg,  const float* __restrict__ Wout)
{
    int f = blockIdx.x * 256 + threadIdx.x;       // 6 * 128 * 64 = 49152
    int m = f >> 13;
    int rem = f & 8191;
    int h = rem >> 6, c2 = rem & 63;
    const float* W = (m == 0) ? Wa1 : (m == 1) ? Wa2 : (m == 2) ? Wb1 :
                     (m == 3) ? Wb2 : (m == 4) ? Wg : Wout;
    float x0 = W[h * 128 + c2 * 2], x1 = W[h * 128 + c2 * 2 + 1];
    unsigned hi, lo; split2(x0, x1, hi, lo);
    char* basep = g_wsp + (size_t)m * WMAT;
    *(unsigned*)(basep + h * 272 + c2 * 4)          = hi;
    *(unsigned*)(basep + WPLANE + h * 272 + c2 * 4) = lo;
}

// ===========================================================================
// Kernel 1: LN(z) + 5 projections. 512 thr (16 warps m16 x n64).
// smem: A hi/lo (69632) | Bbuf0 (69632) | Bbuf1 (69632, aliases Zf fp32) | params
// ===========================================================================
#define P_A   0
#define P_B0  69632
#define P_B1  139264
#define P_GIN 208896
#define P_BIN 209408
#define P_SMEM 209920

__global__ __launch_bounds__(512, 1) void proj_kernel(
    const float* __restrict__ z,
    const float* __restrict__ gin, const float* __restrict__ bin)
{
    extern __shared__ char sm[];
    const unsigned SB = smem_u32(sm);
    const int tid = threadIdx.x, lane = tid & 31, w = tid >> 5;
    const int g = lane >> 2, t2 = (lane & 3) * 2;
    const int wm = w >> 1, wn = w & 1;
    const int m0 = wm * 16;
    const size_t base = (size_t)blockIdx.x * 128;

    // prefetch W0 into B0 immediately
    for (int t = tid; t < WMAT / 16; t += 512)
        cp16(SB + P_B0 + t * 16, g_wsp + (size_t)t * 16);
    CP_COMMIT();

    if (tid < 128) {
        ((float*)(sm + P_GIN))[tid] = gin[tid];
        ((float*)(sm + P_BIN))[tid] = bin[tid];
    }

    // stage z tile fp32 [128][133] over B1
    float* Zf = (float*)(sm + P_B1);
    {
        const float4* z4 = (const float4*)(z + base * 128);
#pragma unroll
        for (int p = 0; p < 8; ++p) {
            int f = tid + p * 512;
            float4 v = z4[f];
            int ij = f >> 5, c4 = (f & 31) * 4;
            float* d = &Zf[ij * 133 + c4];
            d[0] = v.x; d[1] = v.y; d[2] = v.z; d[3] = v.w;
        }
    }
    __syncthreads();

    // LN: 4 threads per row; write split A tiles
    {
        int row = tid >> 2, q = tid & 3;
        float s = 0.f, s2 = 0.f;
#pragma unroll
        for (int c = 0; c < 32; ++c) { float x = Zf[row * 133 + q * 32 + c]; s += x; s2 += x * x; }
        s  += __shfl_xor_sync(0xffffffffu, s, 1);  s2 += __shfl_xor_sync(0xffffffffu, s2, 1);
        s  += __shfl_xor_sync(0xffffffffu, s, 2);  s2 += __shfl_xor_sync(0xffffffffu, s2, 2);
        float mu = s * (1.f / 128.f);
        float rs = rsqrtf(fmaf(-mu, mu, s2 * (1.f / 128.f)) + 1e-5f);
        const float* G  = (const float*)(sm + P_GIN);
        const float* Bv = (const float*)(sm + P_BIN);
#pragma unroll
        for (int c2 = 0; c2 < 16; ++c2) {
            int c = q * 32 + c2 * 2;
            float x0 = (Zf[row * 133 + c]     - mu) * rs * G[c]     + Bv[c];
            float x1 = (Zf[row * 133 + c + 1] - mu) * rs * G[c + 1] + Bv[c + 1];
            unsigned hi, lo; split2(x0, x1, hi, lo);
            *(unsigned*)(sm + P_A         + (row * STR + c) * 2) = hi;
            *(unsigned*)(sm + P_A + WPLANE + (row * STR + c) * 2) = lo;
        }
    }
    __syncthreads();   // A ready; Zf consumed

    float keep[8][4];

    for (int m = 0; m < 5; ++m) {
        CP_WAIT0();
        __syncthreads();          // W[m] visible; all warps past previous MMA
        if (m < 4) {              // prefetch W[m+1] into the other buffer
            const unsigned dstb = ((m + 1) & 1) ? P_B1 : P_B0;
            const char* srcb = g_wsp + (size_t)(m + 1) * WMAT;
            for (int t = tid; t < WMAT / 16; t += 512)
                cp16(SB + dstb + t * 16, srcb + (size_t)t * 16);
            CP_COMMIT();
        }
        const unsigned BHI = ((m & 1) ? P_B1 : P_B0);
        const unsigned BLO = BHI + WPLANE;

        float acc[8][4];
#pragma unroll
        for (int i = 0; i < 8; ++i)
#pragma unroll
            for (int j = 0; j < 4; ++j) acc[i][j] = 0.f;

#pragma unroll
        for (int ks = 0; ks < 8; ++ks) {
            const int k0 = ks * 16;
            unsigned ah[4], al[4];
            ldsm4(ah, ldsm_addr(SB + P_A,          lane, m0, k0, STR));
            ldsm4(al, ldsm_addr(SB + P_A + WPLANE, lane, m0, k0, STR));
#pragma unroll
            for (int nb = 0; nb < 4; ++nb) {
                const int n0 = wn * 64 + nb * 16;
                unsigned bh[4], bl[4];
                ldsm4(bh, ldsm_addr(SB + BHI, lane, n0, k0, STR));
                ldsm4(bl, ldsm_addr(SB + BLO, lane, n0, k0, STR));
                mma_bf16(acc[nb * 2],     ah, bh[0], bh[2]);
                mma_bf16(acc[nb * 2],     ah, bl[0], bl[2]);
                mma_bf16(acc[nb * 2],     al, bh[0], bh[2]);
                mma_bf16(acc[nb * 2 + 1], ah, bh[1], bh[3]);
                mma_bf16(acc[nb * 2 + 1], ah, bl[1], bl[3]);
                mma_bf16(acc[nb * 2 + 1], al, bh[1], bh[3]);
            }
        }

        if (m == 0 || m == 2) {
#pragma unroll
            for (int i = 0; i < 8; ++i)
#pragma unroll
                for (int j = 0; j < 4; ++j) keep[i][j] = sigm(acc[i][j]);
        } else if (m == 1 || m == 3) {
            __nv_bfloat16* ph = (m == 1) ? g_ah : g_bh;
            __nv_bfloat16* pl = (m == 1) ? g_al : g_bl;
            const size_t ijA = base + m0 + g, ijB = ijA + 8;
#pragma unroll
            for (int nt = 0; nt < 8; ++nt) {
                const size_t d0 = (size_t)(wn * 64 + nt * 8 + t2);
                store_split(ph, pl, d0 * NN + ijA,       keep[nt][0] * acc[nt][0]);
                store_split(ph, pl, (d0 + 1) * NN + ijA, keep[nt][1] * acc[nt][1]);
                store_split(ph, pl, d0 * NN + ijB,       keep[nt][2] * acc[nt][2]);
                store_split(ph, pl, (d0 + 1) * NN + ijB, keep[nt][3] * acc[nt][3]);
            }
        } else {
            const size_t ijA = base + m0 + g, ijB = ijA + 8;
#pragma unroll
            for (int nt = 0; nt < 8; ++nt) {
                const int c0 = wn * 64 + nt * 8 + t2;
                *(float2*)&g_gate[ijA * 128 + c0] = make_float2(sigm(acc[nt][0]), sigm(acc[nt][1]));
                *(float2*)&g_gate[ijB * 128 + c0] = make_float2(sigm(acc[nt][2]), sigm(acc[nt][3]));
            }
        }
    }
}

// ===========================================================================
// Kernel 2: einsum, 128x128 tile, 256 thr (8 warps 2x4), cp.async double buffer
// buffer: AHI 0 | ALO 18432 | BHI 36864 | BLO 55296   (73728 per buffer, x2)
// ===========================================================================
#define ESTR 72
#define E_BUF 73728
#define E_SMEM (2*E_BUF)

__global__ __launch_bounds__(256, 1) void einsum_kernel()
{
    extern __shared__ char sm[];
    const unsigned SB = smem_u32(sm);
    const int tid = threadIdx.x, lane = tid & 31, w = tid >> 5;
    const int g = lane >> 2, t2 = (lane & 3) * 2;
    const int wr = w >> 2, wc = w & 3;
    const int m0w = wr * 64, n0w = wc * 32;
    const int d = blockIdx.z, i0 = blockIdx.y * 128, j0 = blockIdx.x * 128;

    const __nv_bfloat16* pah = g_ah + (size_t)d * NN + (size_t)i0 * Nn;
    const __nv_bfloat16* pal = g_al + (size_t)d * NN + (size_t)i0 * Nn;
    const __nv_bfloat16* pbh = g_bh + (size_t)d * NN + (size_t)j0 * Nn;
    const __nv_bfloat16* pbl = g_bl + (size_t)d * NN + (size_t)j0 * Nn;

    // stage chunk c into buffer b
    auto stage = [&](int c, int b) {
        const int k0 = c * 64;
        const unsigned dstb = SB + b * E_BUF;
#pragma unroll
        for (int p = 0; p < 4; ++p) {
            const __nv_bfloat16* src = (p == 0) ? pah : (p == 1) ? pal : (p == 2) ? pbh : pbl;
#pragma unroll
            for (int q = 0; q < 4; ++q) {
                int rem = q * 256 + tid;
                int r = rem >> 3, sg = rem & 7;
                cp16(dstb + p * 18432 + (r * ESTR + sg * 8) * 2,
                     src + (size_t)r * Nn + k0 + sg * 8);
            }
        }
        CP_COMMIT();
    };

    float acc[16][4];
#pragma unroll
    for (int i = 0; i < 16; ++i)
#pragma unroll
        for (int j = 0; j < 4; ++j) acc[i][j] = 0.f;

    stage(0, 0);

    for (int c = 0; c < 6; ++c) {
        CP_WAIT0();
        __syncthreads();
        if (c < 5) stage(c + 1, (c + 1) & 1);

        const unsigned B = SB + (c & 1) * E_BUF;
#pragma unroll
        for (int ks = 0; ks < 4; ++ks) {
            const int k0 = ks * 16;
            unsigned bh[4][2], bl[4][2];
#pragma unroll
            for (int nb = 0; nb < 2; ++nb) {
                unsigned tb[4];
                ldsm4(tb, ldsm_addr(B + 36864, lane, n0w + nb * 16, k0, ESTR));
                bh[nb * 2][0] = tb[0]; bh[nb * 2][1] = tb[2];
                bh[nb * 2 + 1][0] = tb[1]; bh[nb * 2 + 1][1] = tb[3];
                ldsm4(tb, ldsm_addr(B + 55296, lane, n0w + nb * 16, k0, ESTR));
                bl[nb * 2][0] = tb[0]; bl[nb * 2][1] = tb[2];
                bl[nb * 2 + 1][0] = tb[1]; bl[nb * 2 + 1][1] = tb[3];
            }
#pragma unroll
            for (int mt = 0; mt < 4; ++mt) {
                unsigned ah[4], al[4];
                ldsm4(ah, ldsm_addr(B,         lane, m0w + mt * 16, k0, ESTR));
                ldsm4(al, ldsm_addr(B + 18432, lane, m0w + mt * 16, k0, ESTR));
#pragma unroll
                for (int n = 0; n < 4; ++n) {
                    mma_bf16(acc[mt * 4 + n], ah, bh[n][0], bh[n][1]);
                    mma_bf16(acc[mt * 4 + n], ah, bl[n][0], bl[n][1]);
                    mma_bf16(acc[mt * 4 + n], al, bh[n][0], bh[n][1]);
                }
            }
        }
    }

    float* plane = g_s + (size_t)d * NN;
#pragma unroll
    for (int mt = 0; mt < 4; ++mt)
#pragma unroll
        for (int n = 0; n < 4; ++n) {
            int row = m0w + mt * 16 + g;
            int col = n0w + n * 8 + t2;
            float* pr = plane + (size_t)(i0 + row) * Nn + (j0 + col);
            *(float2*)pr            = make_float2(acc[mt * 4 + n][0], acc[mt * 4 + n][1]);
            *(float2*)(pr + 8 * Nn) = make_float2(acc[mt * 4 + n][2], acc[mt * 4 + n][3]);
        }
}

// ===========================================================================
// Kernel 3: LN(s over d) + Wout + gate. 512 thr, Wout prefetched via cp.async
// smem: A (69632) | W (69632) | Sf fp32 [128][133] (68096) | params
// ===========================================================================
#define O_A  0
#define O_W  69632
#define O_SF 139264
#define O_G  207360
#define O_B2 207872
#define O_SMEM 208384

__global__ __launch_bounds__(512, 1) void out_kernel(
    const float* __restrict__ gout, const float* __restrict__ bout,
    float* __restrict__ outp)
{
    extern __shared__ char sm[];
    const unsigned SB = smem_u32(sm);
    const int tid = threadIdx.x, lane = tid & 31, w = tid >> 5;
    const int g = lane >> 2, t2 = (lane & 3) * 2;
    const int wm = w >> 1, wn = w & 1;
    const int m0 = wm * 16;
    const size_t base = (size_t)blockIdx.x * 128;

    // prefetch Wout (matrix index 5)
    for (int t = tid; t < WMAT / 16; t += 512)
        cp16(SB + O_W + t * 16, g_wsp + 5 * (size_t)WMAT + t * 16);
    CP_COMMIT();

    if (tid < 128) {
        ((float*)(sm + O_G))[tid]  = gout[tid];
        ((float*)(sm + O_B2))[tid] = bout[tid];
    }

    float* Sf = (float*)(sm + O_SF);
#pragma unroll 4
    for (int p = 0; p < 32; ++p) {
        int f = tid + p * 512;
        int ij = f & 127, dd = f >> 7;
        Sf[ij * 133 + dd] = g_s[(size_t)dd * NN + base + ij];
    }
    __syncthreads();

    {
        int row = tid >> 2, q = tid & 3;
        float s = 0.f, s2 = 0.f;
#pragma unroll
        for (int c = 0; c < 32; ++c) { float x = Sf[row * 133 + q * 32 + c]; s += x; s2 += x * x; }
        s  += __shfl_xor_sync(0xffffffffu, s, 1);  s2 += __shfl_xor_sync(0xffffffffu, s2, 1);
        s  += __shfl_xor_sync(0xffffffffu, s, 2);  s2 += __shfl_xor_sync(0xffffffffu, s2, 2);
        float mu = s * (1.f / 128.f);
        float rs = rsqrtf(fmaf(-mu, mu, s2 * (1.f / 128.f)) + 1e-5f);
        const float* G  = (const float*)(sm + O_G);
        const float* Bv = (const float*)(sm + O_B2);
#pragma unroll
        for (int c2 = 0; c2 < 16; ++c2) {
            int c = q * 32 + c2 * 2;
            float x0 = (Sf[row * 133 + c]     - mu) * rs * G[c]     + Bv[c];
            float x1 = (Sf[row * 133 + c + 1] - mu) * rs * G[c + 1] + Bv[c + 1];
            unsigned hi, lo; split2(x0, x1, hi, lo);
            *(unsigned*)(sm + O_A          + (row * STR + c) * 2) = hi;
            *(unsigned*)(sm + O_A + WPLANE + (row * STR + c) * 2) = lo;
        }
    }
    CP_WAIT0();
    __syncthreads();

    float acc[8][4];
#pragma unroll
    for (int i = 0; i < 8; ++i)
#pragma unroll
        for (int j = 0; j < 4; ++j) acc[i][j] = 0.f;

#pragma unroll
    for (int ks = 0; ks < 8; ++ks) {
        const int k0 = ks * 16;
        unsigned ah[4], al[4];
        ldsm4(ah, ldsm_addr(SB + O_A,          lane, m0, k0, STR));
        ldsm4(al, ldsm_addr(SB + O_A + WPLANE, lane, m0, k0, STR));
#pragma unroll
        for (int nb = 0; nb < 4; ++nb) {
            const int n0 = wn * 64 + nb * 16;
            unsigned bh[4], bl[4];
            ldsm4(bh, ldsm_addr(SB + O_W,          lane, n0, k0, STR));
            ldsm4(bl, ldsm_addr(SB + O_W + WPLANE, lane, n0, k0, STR));
            mma_bf16(acc[nb * 2],     ah, bh[0], bh[2]);
            mma_bf16(acc[nb * 2],     ah, bl[0], bl[2]);
            mma_bf16(acc[nb * 2],     al, bh[0], bh[2]);
            mma_bf16(acc[nb * 2 + 1], ah, bh[1], bh[3]);
            mma_bf16(acc[nb * 2 + 1], ah, bl[1], bl[3]);
            mma_bf16(acc[nb * 2 + 1], al, bh[1], bh[3]);
        }
    }

    const size_t ijA = base + m0 + g, ijB = ijA + 8;
#pragma unroll
    for (int nt = 0; nt < 8; ++nt) {
        const int c0 = wn * 64 + nt * 8 + t2;
        float2 g0 = *(const float2*)&g_gate[ijA * 128 + c0];
        float2 g1 = *(const float2*)&g_gate[ijB * 128 + c0];
        *(float2*)&outp[ijA * 128 + c0] = make_float2(acc[nt][0] * g0.x, acc[nt][1] * g0.y);
        *(float2*)&outp[ijB * 128 + c0] = make_float2(acc[nt][2] * g1.x, acc[nt][3] * g1.y);
    }
}

// ---------------------------------------------------------------------------
extern "C" void kernel_launch(void* const* d_in, const int* in_sizes, int n_in,
                              void* d_out, int out_size)
{
    const float* z    = (const float*)d_in[0];
    const float* gin  = (const float*)d_in[1];
    const float* bin  = (const float*)d_in[2];
    const float* gout = (const float*)d_in[3];
    const float* bout = (const float*)d_in[4];
    const float* Wa1  = (const float*)d_in[5];
    const float* Wa2  = (const float*)d_in[6];
    const float* Wb1  = (const float*)d_in[7];
    const float* Wb2  = (const float*)d_in[8];
    const float* Wg   = (const float*)d_in[9];
    const float* Wout = (const float*)d_in[10];
    float* out = (float*)d_out;

    cudaFuncSetAttribute(proj_kernel,   cudaFuncAttributeMaxDynamicSharedMemorySize, P_SMEM);
    cudaFuncSetAttribute(einsum_kernel, cudaFuncAttributeMaxDynamicSharedMemorySize, E_SMEM);
    cudaFuncSetAttribute(out_kernel,    cudaFuncAttributeMaxDynamicSharedMemorySize, O_SMEM);

    split_weights_kernel<<<192, 256>>>(Wa1, Wa2, Wb1, Wb2, Wg, Wout);
    proj_kernel<<<NN / 128, 512, P_SMEM>>>(z, gin, bin);
    einsum_kernel<<<dim3(Nn / 128, Nn / 128, Cc), 256, E_SMEM>>>();
    out_kernel<<<NN / 128, 512, O_SMEM>>>(gout, bout, out);
}

// round 8
// speedup vs baseline: 5.0885x; 1.1678x over previous
#include <cuda_runtime.h>
#include <cuda_bf16.h>
#include <math.h>

#define Nn 384
#define Cc 128
#define NN (Nn*Nn)   // 147456

// ---------------- global scratch (no allocations allowed) ------------------
__device__ __nv_bfloat16 g_ah[(size_t)Cc*NN];
__device__ __nv_bfloat16 g_al[(size_t)Cc*NN];
__device__ __nv_bfloat16 g_bh[(size_t)Cc*NN];
__device__ __nv_bfloat16 g_bl[(size_t)Cc*NN];
__device__ float g_gate[(size_t)Cc*NN];
__device__ float g_s[(size_t)Cc*NN];

// Pre-split weights as smem tile image: per matrix hi plane [128 x 272B], then lo.
#define WPLANE 34816
#define WMAT   (2*WPLANE)
__device__ __align__(16) char g_wsp[6*WMAT];

// ---------------- helpers ---------------------------------------------------
__device__ __forceinline__ unsigned smem_u32(const void* p) {
    unsigned a;
    asm("{ .reg .u64 t; cvta.to.shared.u64 t, %1; cvt.u32.u64 %0, t; }" : "=r"(a) : "l"(p));
    return a;
}
__device__ __forceinline__ void ldsm4(unsigned r[4], unsigned addr) {
    asm volatile("ldmatrix.sync.aligned.m8n8.x4.shared.b16 {%0,%1,%2,%3}, [%4];"
        : "=r"(r[0]), "=r"(r[1]), "=r"(r[2]), "=r"(r[3]) : "r"(addr));
}
__device__ __forceinline__ void mma_bf16(float c[4], const unsigned a[4], unsigned b0, unsigned b1) {
    asm volatile("mma.sync.aligned.m16n8k16.row.col.f32.bf16.bf16.f32 "
        "{%0,%1,%2,%3}, {%4,%5,%6,%7}, {%8,%9}, {%0,%1,%2,%3};"
        : "+f"(c[0]), "+f"(c[1]), "+f"(c[2]), "+f"(c[3])
        : "r"(a[0]), "r"(a[1]), "r"(a[2]), "r"(a[3]), "r"(b0), "r"(b1));
}
__device__ __forceinline__ unsigned ldsm_addr(unsigned base, int lane, int r0, int c0, int S) {
    int row = r0 + (lane & 7) + ((lane >> 3) & 1) * 8;
    int col = c0 + ((lane >> 4) << 3);
    return base + (unsigned)((row * S + col) * 2);
}
__device__ __forceinline__ void cp16(unsigned dst, const void* src) {
    asm volatile("cp.async.cg.shared.global [%0], [%1], 16;" :: "r"(dst), "l"(src));
}
#define CP_COMMIT() asm volatile("cp.async.commit_group;" ::: "memory")
#define CP_WAIT0()  asm volatile("cp.async.wait_group 0;" ::: "memory")
#define CP_WAIT1()  asm volatile("cp.async.wait_group 1;" ::: "memory")

__device__ __forceinline__ float sigm(float x) { return 1.f / (1.f + __expf(-x)); }

__device__ __forceinline__ void split2(float a, float b, unsigned& hi, unsigned& lo) {
    __nv_bfloat16 ha = __float2bfloat16(a), hb = __float2bfloat16(b);
    float ra = a - __bfloat162float(ha), rb = b - __bfloat162float(hb);
    __nv_bfloat16 la = __float2bfloat16(ra), lb = __float2bfloat16(rb);
    hi = (unsigned)__bfloat16_as_ushort(ha) | ((unsigned)__bfloat16_as_ushort(hb) << 16);
    lo = (unsigned)__bfloat16_as_ushort(la) | ((unsigned)__bfloat16_as_ushort(lb) << 16);
}

#define STR 136      // bf16 row stride for 128-col tiles (272B)
#define APL 17408    // 64-row A plane (64*272)

// ===========================================================================
// Kernel 0: split 6 weight matrices into smem-image layout
// ===========================================================================
__global__ __launch_bounds__(256) void split_weights_kernel(
    const float* __restrict__ Wa1, const float* __restrict__ Wa2,
    const float* __restrict__ Wb1, const float* __restrict__ Wb2,
    const float* __restrict__ Wg,  const float* __restrict__ Wout)
{
    int f = blockIdx.x * 256 + threadIdx.x;       // 6*128*64 = 49152
    int m = f >> 13;
    int rem = f & 8191;
    int h = rem >> 6, c2 = rem & 63;
    const float* W = (m == 0) ? Wa1 : (m == 1) ? Wa2 : (m == 2) ? Wb1 :
                     (m == 3) ? Wb2 : (m == 4) ? Wg : Wout;
    float x0 = W[h * 128 + c2 * 2], x1 = W[h * 128 + c2 * 2 + 1];
    unsigned hi, lo; split2(x0, x1, hi, lo);
    char* basep = g_wsp + (size_t)m * WMAT;
    *(unsigned*)(basep + h * 272 + c2 * 4)          = hi;
    *(unsigned*)(basep + WPLANE + h * 272 + c2 * 4) = lo;
}

// ===========================================================================
// Kernel 1: LN(z) + 5 projections. 64-row tiles, 256 thr (8 warps m16 x n64),
// occupancy 2. smem: A hi/lo (34816) | B/W region (69632, aliases Zf + stage) | params
// ===========================================================================
#define P_A   0
#define P_B   34816
#define P_GIN 104448
#define P_BIN 104960
#define P_SMEM 105472

__global__ __launch_bounds__(256, 2) void proj_kernel(
    const float* __restrict__ z,
    const float* __restrict__ gin, const float* __restrict__ bin)
{
    extern __shared__ char sm[];
    const unsigned SB = smem_u32(sm);
    const int tid = threadIdx.x, lane = tid & 31, w = tid >> 5;
    const int g = lane >> 2, t2 = (lane & 3) * 2;
    const int wm = w >> 1, wn = w & 1;
    const int m0 = wm * 16;
    const size_t base = (size_t)blockIdx.x * 64;

    if (tid < 128) {
        ((float*)(sm + P_GIN))[tid] = gin[tid];
        ((float*)(sm + P_BIN))[tid] = bin[tid];
    }

    // stage z tile fp32 [64][133] in B region
    float* Zf = (float*)(sm + P_B);
    {
        const float4* z4 = (const float4*)(z + base * 128);
#pragma unroll
        for (int p = 0; p < 8; ++p) {
            int f = tid + p * 256;
            float4 v = z4[f];
            int ij = f >> 5, c4 = (f & 31) * 4;
            float* d = &Zf[ij * 133 + c4];
            d[0] = v.x; d[1] = v.y; d[2] = v.z; d[3] = v.w;
        }
    }
    __syncthreads();

    // LN: 4 threads per row, write split A tiles
    {
        int row = tid >> 2, q = tid & 3;
        float s = 0.f, s2 = 0.f;
#pragma unroll
        for (int c = 0; c < 32; ++c) { float x = Zf[row * 133 + q * 32 + c]; s += x; s2 += x * x; }
        s  += __shfl_xor_sync(0xffffffffu, s, 1);  s2 += __shfl_xor_sync(0xffffffffu, s2, 1);
        s  += __shfl_xor_sync(0xffffffffu, s, 2);  s2 += __shfl_xor_sync(0xffffffffu, s2, 2);
        float mu = s * (1.f / 128.f);
        float rs = rsqrtf(fmaf(-mu, mu, s2 * (1.f / 128.f)) + 1e-5f);
        const float* G  = (const float*)(sm + P_GIN);
        const float* Bv = (const float*)(sm + P_BIN);
#pragma unroll
        for (int c2 = 0; c2 < 16; ++c2) {
            int c = q * 32 + c2 * 2;
            float x0 = (Zf[row * 133 + c]     - mu) * rs * G[c]     + Bv[c];
            float x1 = (Zf[row * 133 + c + 1] - mu) * rs * G[c + 1] + Bv[c + 1];
            unsigned hi, lo; split2(x0, x1, hi, lo);
            *(unsigned*)(sm + P_A       + (row * STR + c) * 2) = hi;
            *(unsigned*)(sm + P_A + APL + (row * STR + c) * 2) = lo;
        }
    }
    __syncthreads();   // A ready; B region (Zf) free

    float keep[8][4];

    for (int m = 0; m < 5; ++m) {
        // load W[m] into B region (single buffer; cross-CTA overlap via occupancy 2)
        {
            const char* srcb = g_wsp + (size_t)m * WMAT;
#pragma unroll
            for (int q = 0; q < 17; ++q) {
                int t = tid + q * 256;
                cp16(SB + P_B + t * 16, srcb + (size_t)t * 16);
            }
            CP_COMMIT();
            CP_WAIT0();
        }
        __syncthreads();

        float acc[8][4];
#pragma unroll
        for (int i = 0; i < 8; ++i)
#pragma unroll
            for (int j = 0; j < 4; ++j) acc[i][j] = 0.f;

#pragma unroll
        for (int ks = 0; ks < 8; ++ks) {
            const int k0 = ks * 16;
            unsigned ah[4], al[4];
            ldsm4(ah, ldsm_addr(SB + P_A,       lane, m0, k0, STR));
            ldsm4(al, ldsm_addr(SB + P_A + APL, lane, m0, k0, STR));
#pragma unroll
            for (int nb = 0; nb < 4; ++nb) {
                const int n0 = wn * 64 + nb * 16;
                unsigned bh[4], bl[4];
                ldsm4(bh, ldsm_addr(SB + P_B,          lane, n0, k0, STR));
                ldsm4(bl, ldsm_addr(SB + P_B + WPLANE, lane, n0, k0, STR));
                mma_bf16(acc[nb * 2],     ah, bh[0], bh[2]);
                mma_bf16(acc[nb * 2],     ah, bl[0], bl[2]);
                mma_bf16(acc[nb * 2],     al, bh[0], bh[2]);
                mma_bf16(acc[nb * 2 + 1], ah, bh[1], bh[3]);
                mma_bf16(acc[nb * 2 + 1], ah, bl[1], bl[3]);
                mma_bf16(acc[nb * 2 + 1], al, bh[1], bh[3]);
            }
        }
        __syncthreads();   // all warps done reading B

        if (m == 0 || m == 2) {
#pragma unroll
            for (int i = 0; i < 8; ++i)
#pragma unroll
                for (int j = 0; j < 4; ++j) keep[i][j] = sigm(acc[i][j]);
        } else if (m == 1 || m == 3) {
            // transpose through smem stage in B region: [d][ij], 144B rows
            __nv_bfloat16* stH = (__nv_bfloat16*)(sm + P_B);
            __nv_bfloat16* stL = (__nv_bfloat16*)(sm + P_B + 18432);
            const int ijA = m0 + g, ijB = ijA + 8;
#pragma unroll
            for (int nt = 0; nt < 8; ++nt) {
                const int d0 = wn * 64 + nt * 8 + t2;
                float v00 = keep[nt][0] * acc[nt][0];
                float v01 = keep[nt][1] * acc[nt][1];
                float v10 = keep[nt][2] * acc[nt][2];
                float v11 = keep[nt][3] * acc[nt][3];
                __nv_bfloat16 h;
                h = __float2bfloat16(v00); stH[d0 * 72 + ijA] = h;
                stL[d0 * 72 + ijA] = __float2bfloat16(v00 - __bfloat162float(h));
                h = __float2bfloat16(v01); stH[(d0 + 1) * 72 + ijA] = h;
                stL[(d0 + 1) * 72 + ijA] = __float2bfloat16(v01 - __bfloat162float(h));
                h = __float2bfloat16(v10); stH[d0 * 72 + ijB] = h;
                stL[d0 * 72 + ijB] = __float2bfloat16(v10 - __bfloat162float(h));
                h = __float2bfloat16(v11); stH[(d0 + 1) * 72 + ijB] = h;
                stL[(d0 + 1) * 72 + ijB] = __float2bfloat16(v11 - __bfloat162float(h));
            }
            __syncthreads();
            __nv_bfloat16* ph = (m == 1) ? g_ah : g_bh;
            __nv_bfloat16* pl = (m == 1) ? g_al : g_bl;
#pragma unroll
            for (int p = 0; p < 8; ++p) {
                int f = tid + p * 256;          // 0..2047
                int plane = f >> 10, rem = f & 1023;
                int d = rem >> 3, u = rem & 7;
                uint4 v = *(const uint4*)(sm + P_B + plane * 18432 + d * 144 + u * 16);
                __nv_bfloat16* gp = plane ? pl : ph;
                *(uint4*)(gp + (size_t)d * NN + base + u * 8) = v;
            }
        } else {
            const size_t ijA = base + m0 + g, ijB = ijA + 8;
#pragma unroll
            for (int nt = 0; nt < 8; ++nt) {
                const int c0 = wn * 64 + nt * 8 + t2;
                *(float2*)&g_gate[ijA * 128 + c0] = make_float2(sigm(acc[nt][0]), sigm(acc[nt][1]));
                *(float2*)&g_gate[ijB * 128 + c0] = make_float2(sigm(acc[nt][2]), sigm(acc[nt][3]));
            }
        }
        __syncthreads();   // B region free for next matrix
    }
}

// ===========================================================================
// Kernel 2: einsum, 128x128 tile, 256 thr (8 warps 2x4), K chunks of 32,
// cp.async double buffer 2x40KB -> occupancy 2.
// buffer: AHI 0 | ALO 10240 | BHI 20480 | BLO 30720  (row stride 40 elems = 80B)
// ===========================================================================
#define E_BUF 40960
#define E_SMEM (2*E_BUF)

__global__ __launch_bounds__(256, 2) void einsum_kernel()
{
    extern __shared__ char sm[];
    const unsigned SB = smem_u32(sm);
    const int tid = threadIdx.x, lane = tid & 31, w = tid >> 5;
    const int g = lane >> 2, t2 = (lane & 3) * 2;
    const int wr = w >> 2, wc = w & 3;
    const int m0w = wr * 64, n0w = wc * 32;
    const int d = blockIdx.z, i0 = blockIdx.y * 128, j0 = blockIdx.x * 128;

    const __nv_bfloat16* pah = g_ah + (size_t)d * NN + (size_t)i0 * Nn;
    const __nv_bfloat16* pal = g_al + (size_t)d * NN + (size_t)i0 * Nn;
    const __nv_bfloat16* pbh = g_bh + (size_t)d * NN + (size_t)j0 * Nn;
    const __nv_bfloat16* pbl = g_bl + (size_t)d * NN + (size_t)j0 * Nn;

    auto stage = [&](int c, int b) {
        const int k0 = c * 32;
        const unsigned dstb = SB + b * E_BUF;
#pragma unroll
        for (int p = 0; p < 4; ++p) {
            const __nv_bfloat16* src = (p == 0) ? pah : (p == 1) ? pal : (p == 2) ? pbh : pbl;
#pragma unroll
            for (int q = 0; q < 2; ++q) {
                int u = q * 256 + tid;      // 0..511
                int r = u >> 2, sg = u & 3;
                cp16(dstb + p * 10240 + r * 80 + sg * 16,
                     src + (size_t)r * Nn + k0 + sg * 8);
            }
        }
        CP_COMMIT();
    };

    float acc[16][4];
#pragma unroll
    for (int i = 0; i < 16; ++i)
#pragma unroll
        for (int j = 0; j < 4; ++j) acc[i][j] = 0.f;

    stage(0, 0);
    stage(1, 1);

    for (int c = 0; c < 12; ++c) {
        if (c < 11) { CP_WAIT1(); } else { CP_WAIT0(); }
        __syncthreads();

        const unsigned B = SB + (c & 1) * E_BUF;
#pragma unroll
        for (int ks = 0; ks < 2; ++ks) {
            const int k0 = ks * 16;
            unsigned bh[4][2], bl[4][2];
#pragma unroll
            for (int nb = 0; nb < 2; ++nb) {
                unsigned tb[4];
                ldsm4(tb, ldsm_addr(B + 20480, lane, n0w + nb * 16, k0, 40));
                bh[nb * 2][0] = tb[0]; bh[nb * 2][1] = tb[2];
                bh[nb * 2 + 1][0] = tb[1]; bh[nb * 2 + 1][1] = tb[3];
                ldsm4(tb, ldsm_addr(B + 30720, lane, n0w + nb * 16, k0, 40));
                bl[nb * 2][0] = tb[0]; bl[nb * 2][1] = tb[2];
                bl[nb * 2 + 1][0] = tb[1]; bl[nb * 2 + 1][1] = tb[3];
            }
#pragma unroll
            for (int mt = 0; mt < 4; ++mt) {
                unsigned ah[4], al[4];
                ldsm4(ah, ldsm_addr(B,         lane, m0w + mt * 16, k0, 40));
                ldsm4(al, ldsm_addr(B + 10240, lane, m0w + mt * 16, k0, 40));
#pragma unroll
                for (int n = 0; n < 4; ++n) {
                    mma_bf16(acc[mt * 4 + n], ah, bh[n][0], bh[n][1]);
                    mma_bf16(acc[mt * 4 + n], ah, bl[n][0], bl[n][1]);
                    mma_bf16(acc[mt * 4 + n], al, bh[n][0], bh[n][1]);
                }
            }
        }
        __syncthreads();
        if (c + 2 < 12) stage(c + 2, c & 1);
    }

    float* plane = g_s + (size_t)d * NN;
#pragma unroll
    for (int mt = 0; mt < 4; ++mt)
#pragma unroll
        for (int n = 0; n < 4; ++n) {
            int row = m0w + mt * 16 + g;
            int col = n0w + n * 8 + t2;
            float* pr = plane + (size_t)(i0 + row) * Nn + (j0 + col);
            *(float2*)pr            = make_float2(acc[mt * 4 + n][0], acc[mt * 4 + n][1]);
            *(float2*)(pr + 8 * Nn) = make_float2(acc[mt * 4 + n][2], acc[mt * 4 + n][3]);
        }
}

// ===========================================================================
// Kernel 3: LN(s over d) + Wout + gate. 64-row tiles, 256 thr, occupancy 2.
// smem: A hi/lo (34816) | W region (69632, aliases Sf fp32 [64][133]) | params
// ===========================================================================
#define O_A   0
#define O_W   34816
#define O_G   104448
#define O_B2  104960
#define O_SMEM 105472

__global__ __launch_bounds__(256, 2) void out_kernel(
    const float* __restrict__ gout, const float* __restrict__ bout,
    float* __restrict__ outp)
{
    extern __shared__ char sm[];
    const unsigned SB = smem_u32(sm);
    const int tid = threadIdx.x, lane = tid & 31, w = tid >> 5;
    const int g = lane >> 2, t2 = (lane & 3) * 2;
    const int wm = w >> 1, wn = w & 1;
    const int m0 = wm * 16;
    const size_t base = (size_t)blockIdx.x * 64;

    if (tid < 128) {
        ((float*)(sm + O_G))[tid]  = gout[tid];
        ((float*)(sm + O_B2))[tid] = bout[tid];
    }

    // transposed stage: Sf[ij][d] fp32, stride 133, in W region
    float* Sf = (float*)(sm + O_W);
#pragma unroll
    for (int p = 0; p < 32; ++p) {
        int f = tid + p * 256;
        int ij = f & 63, dd = f >> 6;
        Sf[ij * 133 + dd] = g_s[(size_t)dd * NN + base + ij];
    }
    __syncthreads();

    {
        int row = tid >> 2, q = tid & 3;
        float s = 0.f, s2 = 0.f;
#pragma unroll
        for (int c = 0; c < 32; ++c) { float x = Sf[row * 133 + q * 32 + c]; s += x; s2 += x * x; }
        s  += __shfl_xor_sync(0xffffffffu, s, 1);  s2 += __shfl_xor_sync(0xffffffffu, s2, 1);
        s  += __shfl_xor_sync(0xffffffffu, s, 2);  s2 += __shfl_xor_sync(0xffffffffu, s2, 2);
        float mu = s * (1.f / 128.f);
        float rs = rsqrtf(fmaf(-mu, mu, s2 * (1.f / 128.f)) + 1e-5f);
        const float* G  = (const float*)(sm + O_G);
        const float* Bv = (const float*)(sm + O_B2);
#pragma unroll
        for (int c2 = 0; c2 < 16; ++c2) {
            int c = q * 32 + c2 * 2;
            float x0 = (Sf[row * 133 + c]     - mu) * rs * G[c]     + Bv[c];
            float x1 = (Sf[row * 133 + c + 1] - mu) * rs * G[c + 1] + Bv[c + 1];
            unsigned hi, lo; split2(x0, x1, hi, lo);
            *(unsigned*)(sm + O_A       + (row * STR + c) * 2) = hi;
            *(unsigned*)(sm + O_A + APL + (row * STR + c) * 2) = lo;
        }
    }
    __syncthreads();   // Sf consumed -> W region free

    // load Wout (matrix index 5) into W region
    {
        const char* srcb = g_wsp + 5 * (size_t)WMAT;
#pragma unroll
        for (int q = 0; q < 17; ++q) {
            int t = tid + q * 256;
            cp16(SB + O_W + t * 16, srcb + (size_t)t * 16);
        }
        CP_COMMIT();
        CP_WAIT0();
    }
    __syncthreads();

    float acc[8][4];
#pragma unroll
    for (int i = 0; i < 8; ++i)
#pragma unroll
        for (int j = 0; j < 4; ++j) acc[i][j] = 0.f;

#pragma unroll
    for (int ks = 0; ks < 8; ++ks) {
        const int k0 = ks * 16;
        unsigned ah[4], al[4];
        ldsm4(ah, ldsm_addr(SB + O_A,       lane, m0, k0, STR));
        ldsm4(al, ldsm_addr(SB + O_A + APL, lane, m0, k0, STR));
#pragma unroll
        for (int nb = 0; nb < 4; ++nb) {
            const int n0 = wn * 64 + nb * 16;
            unsigned bh[4], bl[4];
            ldsm4(bh, ldsm_addr(SB + O_W,          lane, n0, k0, STR));
            ldsm4(bl, ldsm_addr(SB + O_W + WPLANE, lane, n0, k0, STR));
            mma_bf16(acc[nb * 2],     ah, bh[0], bh[2]);
            mma_bf16(acc[nb * 2],     ah, bl[0], bl[2]);
            mma_bf16(acc[nb * 2],     al, bh[0], bh[2]);
            mma_bf16(acc[nb * 2 + 1], ah, bh[1], bh[3]);
            mma_bf16(acc[nb * 2 + 1], ah, bl[1], bl[3]);
            mma_bf16(acc[nb * 2 + 1], al, bh[1], bh[3]);
        }
    }

    const size_t ijA = base + m0 + g, ijB = ijA + 8;
#pragma unroll
    for (int nt = 0; nt < 8; ++nt) {
        const int c0 = wn * 64 + nt * 8 + t2;
        float2 g0 = *(const float2*)&g_gate[ijA * 128 + c0];
        float2 g1 = *(const float2*)&g_gate[ijB * 128 + c0];
        *(float2*)&outp[ijA * 128 + c0] = make_float2(acc[nt][0] * g0.x, acc[nt][1] * g0.y);
        *(float2*)&outp[ijB * 128 + c0] = make_float2(acc[nt][2] * g1.x, acc[nt][3] * g1.y);
    }
}

// ---------------------------------------------------------------------------
extern "C" void kernel_launch(void* const* d_in, const int* in_sizes, int n_in,
                              void* d_out, int out_size)
{
    const float* z    = (const float*)d_in[0];
    const float* gin  = (const float*)d_in[1];
    const float* bin  = (const float*)d_in[2];
    const float* gout = (const float*)d_in[3];
    const float* bout = (const float*)d_in[4];
    const float* Wa1  = (const float*)d_in[5];
    const float* Wa2  = (const float*)d_in[6];
    const float* Wb1  = (const float*)d_in[7];
    const float* Wb2  = (const float*)d_in[8];
    const float* Wg   = (const float*)d_in[9];
    const float* Wout = (const float*)d_in[10];
    float* out = (float*)d_out;

    cudaFuncSetAttribute(proj_kernel,   cudaFuncAttributeMaxDynamicSharedMemorySize, P_SMEM);
    cudaFuncSetAttribute(einsum_kernel, cudaFuncAttributeMaxDynamicSharedMemorySize, E_SMEM);
    cudaFuncSetAttribute(out_kernel,    cudaFuncAttributeMaxDynamicSharedMemorySize, O_SMEM);

    split_weights_kernel<<<192, 256>>>(Wa1, Wa2, Wb1, Wb2, Wg, Wout);
    proj_kernel<<<NN / 64, 256, P_SMEM>>>(z, gin, bin);
    einsum_kernel<<<dim3(Nn / 128, Nn / 128, Cc), 256, E_SMEM>>>();
    out_kernel<<<NN / 64, 256, O_SMEM>>>(gout, bout, out);
}